// round 3
// baseline (speedup 1.0000x reference)
#include <cuda_runtime.h>
#include <cuda_bf16.h>
#include <math_constants.h>

#define N_USERS       6040
#define NUM_INPUTS    9992          // 6040 + 3952
#define FACT_NUM      16
#define BATCH         4194304
#define NGROUPS       (BATCH / 4)   // 1048576 groups of 4 rows
#define RATING_THRESH 3

#define TPB     512
#define BLOCKS  512                 // 512*512 threads; exactly 4 groups/thread

// Published by fm_fast (all blocks write identical values); consumed by
// fm_general, which runs strictly after on the same stream.
__device__ float g_K;
__device__ int   g_mode;            // 0=general, 1=all 1.0f, 2=all 0.0f

// Per-block computation of K and saturation mode. Cheap: w (40KB) is
// L2-resident after the first block touches it.
template <int NWARP>
__device__ __forceinline__ void compute_mode(const float* __restrict__ w,
                                             const float* __restrict__ emb,
                                             const float* __restrict__ bias,
                                             float& K_out, int& mode_out) {
    __shared__ float s_mn[NWARP], s_mx[NWARP];
    __shared__ float s_K;
    __shared__ int   s_mode;

    const int tid = threadIdx.x;
    float mn = CUDART_INF_F, mx = -CUDART_INF_F;
    for (int i = tid; i < NUM_INPUTS; i += NWARP * 32) {
        float v = __ldg(w + i);
        mn = fminf(mn, v);
        mx = fmaxf(mx, v);
    }
    #pragma unroll
    for (int s = 16; s > 0; s >>= 1) {
        mn = fminf(mn, __shfl_xor_sync(0xffffffffu, mn, s));
        mx = fmaxf(mx, __shfl_xor_sync(0xffffffffu, mx, s));
    }
    if ((tid & 31) == 0) { s_mn[tid >> 5] = mn; s_mx[tid >> 5] = mx; }
    __syncthreads();

    if (tid == 0) {
        #pragma unroll
        for (int i = 1; i < NWARP; ++i) {
            mn = fminf(s_mn[0], s_mn[i]); s_mn[0] = mn;
            mx = fmaxf(s_mx[0], s_mx[i]); s_mx[0] = mx;
        }
        mn = s_mn[0]; mx = s_mx[0];

        const float c0 = (float)(NUM_INPUTS - 2);
        const float c1 = 2.0f;
        float acc = 0.0f;
        #pragma unroll
        for (int k = 0; k < FACT_NUM; ++k) {
            float e0 = __ldg(emb + k);
            float e1 = __ldg(emb + FACT_NUM + k);
            float se = c0 * e0 + c1 * e1;
            float sq = c0 * e0 * e0 + c1 * e1 * e1;
            acc += se * se - sq;
        }
        float K = 0.5f * acc + __ldg(bias);
        // fp32 sigmoid rounds to exactly 1.0f for z > ~17; to 0.0f for z < -88.
        // Linear term bounded by [2*mn, 2*mx]; margins generous.
        int mode = 0;
        if (K + 2.0f * mn > 20.0f)       mode = 1;
        else if (K + 2.0f * mx < -25.0f) mode = 2;
        s_K = K; s_mode = mode;
    }
    __syncthreads();
    K_out = s_K;
    mode_out = s_mode;
}

// ints [12g,12g+12): a=(u0,m0,r0,u1) b=(m1,r1,u2,m2) c=(r2,u3,m3,r3)
__device__ __forceinline__ float4 rec4(const int4& a, const int4& b, const int4& c) {
    float4 r;
    r.x = (a.z >= RATING_THRESH) ? 1.0f : 0.0f;
    r.y = (b.y >= RATING_THRESH) ? 1.0f : 0.0f;
    r.z = (c.x >= RATING_THRESH) ? 1.0f : 0.0f;
    r.w = (c.w >= RATING_THRESH) ? 1.0f : 0.0f;
    return r;
}

// ---------------- Kernel 1: saturated fast path (no 40KB smem) ----------------
__global__ __launch_bounds__(TPB)
void fm_fast(const int4* __restrict__ x4,
             const float* __restrict__ w,
             const float* __restrict__ emb,
             const float* __restrict__ bias,
             float* __restrict__ out) {
    float K; int mode;
    compute_mode<TPB / 32>(w, emb, bias, K, mode);

    // Publish for fm_general (same value from every block; benign).
    if (threadIdx.x == 0) { g_K = K; g_mode = mode; }

    if (mode == 0) return;   // general kernel (next on stream) handles it

    const float ov = (mode == 1) ? 1.0f : 0.0f;
    const float4 oc = make_float4(ov, ov, ov, ov);
    float4* __restrict__ o_out = (float4*)out;
    float4* __restrict__ r_out = (float4*)(out + BATCH);

    const int stride = BLOCKS * TPB;                 // 262144
    const int base   = blockIdx.x * TPB + threadIdx.x;
    #pragma unroll
    for (int chunk = 0; chunk < 2; ++chunk) {
        const int gA = base + (2 * chunk + 0) * stride;
        const int gB = base + (2 * chunk + 1) * stride;
        int4 a0 = x4[3 * gA + 0];
        int4 b0 = x4[3 * gA + 1];
        int4 c0 = x4[3 * gA + 2];
        int4 a1 = x4[3 * gB + 0];
        int4 b1 = x4[3 * gB + 1];
        int4 c1 = x4[3 * gB + 2];
        o_out[gA] = oc;
        o_out[gB] = oc;
        r_out[gA] = rec4(a0, b0, c0);
        r_out[gB] = rec4(a1, b1, c1);
    }
}

// ---------------- Kernel 2: general fallback (smem-staged gathers) ----------------
__device__ __forceinline__ float fast_sigmoid(float z) {
    if (z > 10.0f)  return 1.0f;
    if (z < -10.0f) return 0.0f;
    return 1.0f / (1.0f + __expf(-z));
}

__global__ __launch_bounds__(TPB)
void fm_general(const int4* __restrict__ x4,
                const float* __restrict__ w,
                float* __restrict__ out) {
    if (g_mode != 0) return;   // fast kernel already produced the output
    const float K = g_K;

    __shared__ float sw[NUM_INPUTS];
    for (int i = threadIdx.x; i < NUM_INPUTS; i += TPB)
        sw[i] = w[i];
    __syncthreads();

    float4* __restrict__ o_out = (float4*)out;
    float4* __restrict__ r_out = (float4*)(out + BATCH);

    for (int g = blockIdx.x * TPB + threadIdx.x; g < NGROUPS;
         g += gridDim.x * TPB) {
        int4 a = x4[3 * g + 0];
        int4 b = x4[3 * g + 1];
        int4 c = x4[3 * g + 2];

        float4 o;
        o.x = fast_sigmoid(sw[a.x] + sw[N_USERS + a.y] + K);
        o.y = fast_sigmoid(sw[a.w] + sw[N_USERS + b.x] + K);
        o.z = fast_sigmoid(sw[b.z] + sw[N_USERS + b.w] + K);
        o.w = fast_sigmoid(sw[c.y] + sw[N_USERS + c.z] + K);

        o_out[g] = o;
        r_out[g] = rec4(a, b, c);
    }
}

extern "C" void kernel_launch(void* const* d_in, const int* in_sizes, int n_in,
                              void* d_out, int out_size) {
    const int*   x   = (const int*)d_in[0];     // (BATCH, 3) int32
    const float* emb = (const float*)d_in[1];   // (9992, 16) f32
    const float* lw  = (const float*)d_in[2];   // (1, 9992) f32
    const float* lb  = (const float*)d_in[3];   // (1,) f32
    float*       out = (float*)d_out;           // [out(4M) | recommended(4M)]

    fm_fast<<<BLOCKS, TPB>>>((const int4*)x, lw, emb, lb, out);
    fm_general<<<BLOCKS, TPB>>>((const int4*)x, lw, out);
    (void)in_sizes; (void)n_in; (void)out_size;
}

// round 4
// speedup vs baseline: 1.1210x; 1.1210x over previous
#include <cuda_runtime.h>
#include <cuda_bf16.h>

#define N_USERS       6040
#define NUM_INPUTS    9992          // 6040 + 3952
#define NUM_W4        2498          // NUM_INPUTS / 4 exactly
#define FACT_NUM      16
#define BATCH         4194304
#define NGROUPS       (BATCH / 4)   // 1048576 groups of 4 rows
#define RATING_THRESH 3

#define TPB     512
#define NWARP   (TPB / 32)
#define BLOCKS  512                 // 512*512 threads; exactly 4 groups/thread
#define GSTRIDE (BLOCKS * TPB)      // 262144

// ints [12g,12g+12): a=(u0,m0,r0,u1) b=(m1,r1,u2,m2) c=(r2,u3,m3,r3)
__device__ __forceinline__ float4 rec4(const int4& a, const int4& b, const int4& c) {
    float4 r;
    r.x = (a.z >= RATING_THRESH) ? 1.0f : 0.0f;
    r.y = (b.y >= RATING_THRESH) ? 1.0f : 0.0f;
    r.z = (c.x >= RATING_THRESH) ? 1.0f : 0.0f;
    r.w = (c.w >= RATING_THRESH) ? 1.0f : 0.0f;
    return r;
}

__device__ __forceinline__ float fast_sigmoid(float z) {
    if (z > 10.0f)  return 1.0f;
    if (z < -10.0f) return 0.0f;
    return 1.0f / (1.0f + __expf(-z));
}

__global__ __launch_bounds__(TPB)
void fm_all(const int4* __restrict__ x4,
            const float* __restrict__ w,
            const float* __restrict__ emb,
            const float* __restrict__ bias,
            float* __restrict__ out) {
    // Table only touched on the general path; occupancy at TPB=512 is
    // warp-capped (4 blocks/SM) before it's smem-capped (5), so it's free.
    __shared__ float sw[NUM_INPUTS];
    __shared__ float s_red[NWARP];
    __shared__ float s_K;
    __shared__ int   s_mode;

    const int tid  = threadIdx.x;
    const int base = blockIdx.x * TPB + tid;

    float4* __restrict__ o_out = (float4*)out;
    float4* __restrict__ r_out = (float4*)(out + BATCH);

    // ---- Front-batch chunk-0 streaming loads (overlap the mode scan) ----
    const int g0 = base;
    const int g1 = base + GSTRIDE;
    int4 a0 = x4[3 * g0 + 0];
    int4 b0 = x4[3 * g0 + 1];
    int4 c0 = x4[3 * g0 + 2];
    int4 a1 = x4[3 * g1 + 0];
    int4 b1 = x4[3 * g1 + 1];
    int4 c1 = x4[3 * g1 + 2];

    // ---- Per-block saturation-mode scan: max|w| over linear table ----
    {
        const float4* __restrict__ w4 = (const float4*)w;
        float ma = 0.0f;
        for (int i = tid; i < NUM_W4; i += TPB) {
            float4 v = w4[i];
            ma = fmaxf(ma, fmaxf(fmaxf(fabsf(v.x), fabsf(v.y)),
                                 fmaxf(fabsf(v.z), fabsf(v.w))));
        }
        #pragma unroll
        for (int s = 16; s > 0; s >>= 1)
            ma = fmaxf(ma, __shfl_xor_sync(0xffffffffu, ma, s));
        if ((tid & 31) == 0) s_red[tid >> 5] = ma;
        __syncthreads();
        if (tid == 0) {
            #pragma unroll
            for (int i = 1; i < NWARP; ++i) ma = fmaxf(ma, s_red[i]);
            ma = fmaxf(ma, s_red[0]);

            const float c0f = (float)(NUM_INPUTS - 2);
            const float c1f = 2.0f;
            float acc = 0.0f;
            #pragma unroll
            for (int k = 0; k < FACT_NUM; ++k) {
                float e0 = __ldg(emb + k);
                float e1 = __ldg(emb + FACT_NUM + k);
                float se = c0f * e0 + c1f * e1;
                float sq = c0f * e0 * e0 + c1f * e1 * e1;
                acc += se * se - sq;
            }
            float K = 0.5f * acc + __ldg(bias);
            // fp32 sigmoid rounds to exactly 1.0f for z>~17, 0.0f for z<-88.
            // Linear term bounded by +/- 2*max|w|; margins generous.
            int mode = 0;
            if (K - 2.0f * ma > 20.0f)       mode = 1;
            else if (K + 2.0f * ma < -25.0f) mode = 2;
            s_K = K; s_mode = mode;
        }
        __syncthreads();
    }
    const float K   = s_K;
    const int  mode = s_mode;

    if (mode != 0) {
        // ---- Saturated fast path: constant out, predicate rec ----
        const float ov = (mode == 1) ? 1.0f : 0.0f;
        const float4 oc = make_float4(ov, ov, ov, ov);
        const int g2 = base + 2 * GSTRIDE;
        const int g3 = base + 3 * GSTRIDE;

        // Constant stores have no load dependence — fire them all now.
        o_out[g0] = oc;
        o_out[g1] = oc;
        o_out[g2] = oc;
        o_out[g3] = oc;

        r_out[g0] = rec4(a0, b0, c0);
        r_out[g1] = rec4(a1, b1, c1);

        int4 a2 = x4[3 * g2 + 0];
        int4 b2 = x4[3 * g2 + 1];
        int4 c2 = x4[3 * g2 + 2];
        int4 a3 = x4[3 * g3 + 0];
        int4 b3 = x4[3 * g3 + 1];
        int4 c3 = x4[3 * g3 + 2];

        r_out[g2] = rec4(a2, b2, c2);
        r_out[g3] = rec4(a3, b3, c3);
        return;
    }

    // ---- General fallback: smem-staged table gathers ----
    for (int i = tid; i < NUM_INPUTS; i += TPB)
        sw[i] = w[i];
    __syncthreads();

    // chunk 0 (already loaded)
    {
        float4 o;
        o.x = fast_sigmoid(sw[a0.x] + sw[N_USERS + a0.y] + K);
        o.y = fast_sigmoid(sw[a0.w] + sw[N_USERS + b0.x] + K);
        o.z = fast_sigmoid(sw[b0.z] + sw[N_USERS + b0.w] + K);
        o.w = fast_sigmoid(sw[c0.y] + sw[N_USERS + c0.z] + K);
        o_out[g0] = o;
        r_out[g0] = rec4(a0, b0, c0);

        o.x = fast_sigmoid(sw[a1.x] + sw[N_USERS + a1.y] + K);
        o.y = fast_sigmoid(sw[a1.w] + sw[N_USERS + b1.x] + K);
        o.z = fast_sigmoid(sw[b1.z] + sw[N_USERS + b1.w] + K);
        o.w = fast_sigmoid(sw[c1.y] + sw[N_USERS + c1.z] + K);
        o_out[g1] = o;
        r_out[g1] = rec4(a1, b1, c1);
    }
    #pragma unroll
    for (int k = 2; k < 4; ++k) {
        const int g = base + k * GSTRIDE;
        int4 a = x4[3 * g + 0];
        int4 b = x4[3 * g + 1];
        int4 c = x4[3 * g + 2];
        float4 o;
        o.x = fast_sigmoid(sw[a.x] + sw[N_USERS + a.y] + K);
        o.y = fast_sigmoid(sw[a.w] + sw[N_USERS + b.x] + K);
        o.z = fast_sigmoid(sw[b.z] + sw[N_USERS + b.w] + K);
        o.w = fast_sigmoid(sw[c.y] + sw[N_USERS + c.z] + K);
        o_out[g] = o;
        r_out[g] = rec4(a, b, c);
    }
}

extern "C" void kernel_launch(void* const* d_in, const int* in_sizes, int n_in,
                              void* d_out, int out_size) {
    const int*   x   = (const int*)d_in[0];     // (BATCH, 3) int32
    const float* emb = (const float*)d_in[1];   // (9992, 16) f32
    const float* lw  = (const float*)d_in[2];   // (1, 9992) f32
    const float* lb  = (const float*)d_in[3];   // (1,) f32
    float*       out = (float*)d_out;           // [out(4M) | recommended(4M)]

    fm_all<<<BLOCKS, TPB>>>((const int4*)x, lw, emb, lb, out);
    (void)in_sizes; (void)n_in; (void)out_size;
}

// round 5
// speedup vs baseline: 1.3207x; 1.1782x over previous
#include <cuda_runtime.h>
#include <cuda_bf16.h>

#define N_USERS       6040
#define NUM_INPUTS    9992          // 6040 + 3952
#define NUM_W4        2498          // NUM_INPUTS / 4 exactly
#define FACT_NUM      16
#define BATCH         4194304
#define NGROUPS       (BATCH / 4)   // 1048576 groups of 4 rows
#define RATING_THRESH 3

#define TPB     512
#define NWARP   (TPB / 32)
#define BLOCKS  592                 // 148 SMs * 4 blocks: exactly one balanced wave
#define GSTRIDE (BLOCKS * TPB)      // 303104

// ints [12g,12g+12): a=(u0,m0,r0,u1) b=(m1,r1,u2,m2) c=(r2,u3,m3,r3)
__device__ __forceinline__ float4 rec4(const int4& a, const int4& b, const int4& c) {
    float4 r;
    r.x = (a.z >= RATING_THRESH) ? 1.0f : 0.0f;
    r.y = (b.y >= RATING_THRESH) ? 1.0f : 0.0f;
    r.z = (c.x >= RATING_THRESH) ? 1.0f : 0.0f;
    r.w = (c.w >= RATING_THRESH) ? 1.0f : 0.0f;
    return r;
}

__device__ __forceinline__ float fast_sigmoid(float z) {
    if (z > 10.0f)  return 1.0f;
    if (z < -10.0f) return 0.0f;
    return 1.0f / (1.0f + __expf(-z));
}

__global__ __launch_bounds__(TPB, 4)   // cap at 32 regs -> 64 warps/SM
void fm_all(const int4* __restrict__ x4,
            const float* __restrict__ w,
            const float* __restrict__ emb,
            const float* __restrict__ bias,
            float* __restrict__ out) {
    // Table only touched on the general path. 4 blocks x 40KB = 160KB <= 228KB,
    // so smem is not the occupancy cap; warps are (64/SM).
    __shared__ float sw[NUM_INPUTS];
    __shared__ float s_red[NWARP];
    __shared__ float s_K;
    __shared__ int   s_mode;

    const int tid  = threadIdx.x;
    const int base = blockIdx.x * TPB + tid;

    float4* __restrict__ o_out = (float4*)out;
    float4* __restrict__ r_out = (float4*)(out + BATCH);

    // ---- Preload iteration-0 x (overlaps the w scan below) ----
    int4 a = x4[3 * base + 0];
    int4 b = x4[3 * base + 1];
    int4 c = x4[3 * base + 2];

    // ---- Per-block saturation-mode scan: max|w| ----
    {
        const float4* __restrict__ w4 = (const float4*)w;
        float ma = 0.0f;
        for (int i = tid; i < NUM_W4; i += TPB) {
            float4 v = w4[i];
            ma = fmaxf(ma, fmaxf(fmaxf(fabsf(v.x), fabsf(v.y)),
                                 fmaxf(fabsf(v.z), fabsf(v.w))));
        }
        #pragma unroll
        for (int s = 16; s > 0; s >>= 1)
            ma = fmaxf(ma, __shfl_xor_sync(0xffffffffu, ma, s));
        if ((tid & 31) == 0) s_red[tid >> 5] = ma;
        __syncthreads();
        if (tid == 0) {
            #pragma unroll
            for (int i = 1; i < NWARP; ++i) ma = fmaxf(ma, s_red[i]);
            ma = fmaxf(ma, s_red[0]);

            const float c0f = (float)(NUM_INPUTS - 2);
            const float c1f = 2.0f;
            float acc = 0.0f;
            #pragma unroll
            for (int k = 0; k < FACT_NUM; ++k) {
                float e0 = __ldg(emb + k);
                float e1 = __ldg(emb + FACT_NUM + k);
                float se = c0f * e0 + c1f * e1;
                float sq = c0f * e0 * e0 + c1f * e1 * e1;
                acc += se * se - sq;
            }
            float K = 0.5f * acc + __ldg(bias);
            // fp32 sigmoid rounds to exactly 1.0f for z>~17, 0.0f for z<-88.
            // Linear term bounded by +/- 2*max|w|; margins generous.
            int mode = 0;
            if (K - 2.0f * ma > 20.0f)       mode = 1;
            else if (K + 2.0f * ma < -25.0f) mode = 2;
            s_K = K; s_mode = mode;
        }
        __syncthreads();
    }
    const float K   = s_K;
    const int  mode = s_mode;

    if (mode != 0) {
        // ---- Saturated fast path: constant out, predicate rec ----
        const float ov = (mode == 1) ? 1.0f : 0.0f;
        const float4 oc = make_float4(ov, ov, ov, ov);

        int g = base;
        while (true) {
            o_out[g] = oc;                 // no load dependence
            r_out[g] = rec4(a, b, c);
            g += GSTRIDE;
            if (g >= NGROUPS) break;
            a = x4[3 * g + 0];
            b = x4[3 * g + 1];
            c = x4[3 * g + 2];
        }
        return;
    }

    // ---- General fallback: smem-staged table gathers ----
    for (int i = tid; i < NUM_INPUTS; i += TPB)
        sw[i] = w[i];
    __syncthreads();

    int g = base;
    while (true) {
        float4 o;
        o.x = fast_sigmoid(sw[a.x] + sw[N_USERS + a.y] + K);
        o.y = fast_sigmoid(sw[a.w] + sw[N_USERS + b.x] + K);
        o.z = fast_sigmoid(sw[b.z] + sw[N_USERS + b.w] + K);
        o.w = fast_sigmoid(sw[c.y] + sw[N_USERS + c.z] + K);
        o_out[g] = o;
        r_out[g] = rec4(a, b, c);
        g += GSTRIDE;
        if (g >= NGROUPS) break;
        a = x4[3 * g + 0];
        b = x4[3 * g + 1];
        c = x4[3 * g + 2];
    }
}

extern "C" void kernel_launch(void* const* d_in, const int* in_sizes, int n_in,
                              void* d_out, int out_size) {
    const int*   x   = (const int*)d_in[0];     // (BATCH, 3) int32
    const float* emb = (const float*)d_in[1];   // (9992, 16) f32
    const float* lw  = (const float*)d_in[2];   // (1, 9992) f32
    const float* lb  = (const float*)d_in[3];   // (1,) f32
    float*       out = (float*)d_out;           // [out(4M) | recommended(4M)]

    fm_all<<<BLOCKS, TPB>>>((const int4*)x, lw, emb, lb, out);
    (void)in_sizes; (void)n_in; (void)out_size;
}